// round 4
// baseline (speedup 1.0000x reference)
#include <cuda_runtime.h>
#include <cuda_fp16.h>

#define BATCH 4096
#define TDIM  1024
#define GATES 512
#define CHUNK 128
#define NCH   8

typedef unsigned long long ull;

// ---------- device scratch (no allocation allowed -> __device__ globals) ----
__device__ float  g_pre[(size_t)BATCH * CHUNK * GATES];  // 1 GB staging (per chunk)
__device__ float  g_WT_ih[128 * GATES];                  // [k][g'] fp32, reordered
__device__ __half g_Whh_h[128 * GATES];                  // [k][g'] fp16, reordered
__device__ float  g_bias[GATES];                         // b_ih+b_hh, reordered
__device__ float  g_h[BATCH * 128];
__device__ float  g_c[BATCH * 128];

// ---------- f32x2 helpers ---------------------------------------------------
__device__ __forceinline__ ull pk(float lo, float hi) {
    ull r; unsigned a = __float_as_uint(lo), b = __float_as_uint(hi);
    asm("mov.b64 %0,{%1,%2};" : "=l"(r) : "r"(a), "r"(b));
    return r;
}
__device__ __forceinline__ float2 upk(ull v) {
    unsigned a, b;
    asm("mov.b64 {%0,%1},%2;" : "=r"(a), "=r"(b) : "l"(v));
    return make_float2(__uint_as_float(a), __uint_as_float(b));
}
__device__ __forceinline__ void fma2(ull& d, ull a, ull b) {
    asm("fma.rn.f32x2 %0,%1,%2,%0;" : "+l"(d) : "l"(a), "l"(b));
}
__device__ __forceinline__ float sigf(float x) {
    return __fdividef(1.f, 1.f + __expf(-x));
}
__device__ __forceinline__ float tanhfast(float x) {
    return 1.f - __fdividef(2.f, __expf(2.f * x) + 1.f);
}

// ---------- prep: transpose + reorder weights, g' = 4*cell + gate ----------
__global__ void k_prep(const float* __restrict__ Wih, const float* __restrict__ Whh,
                       const float* __restrict__ bih, const float* __restrict__ bhh) {
    int i = blockIdx.x * 256 + threadIdx.x;     // 128*512 total
    if (i >= 128 * GATES) return;
    int k = i >> 9;          // 0..127 (input dim)
    int p = i & 511;         // reordered gate index
    int j = p >> 2, q = p & 3;
    int go = q * 128 + j;    // original gate row (i,f,g,o quadrants)
    g_WT_ih[k * GATES + p] = Wih[go * 128 + k];
    g_Whh_h[k * GATES + p] = __float2half(Whh[go * 128 + k]);
    if (k == 0) g_bias[p] = bih[go] + bhh[go];
}

__global__ void k_zero() {
    int i = blockIdx.x * 256 + threadIdx.x;
    if (i < BATCH * 128) { g_h[i] = 0.f; g_c[i] = 0.f; }
}

// ---------- phase 1: pre = relu(x@We^T+be) @ Wih^T + bias -------------------
// CTA tile: 64 rows (one tloc, 64 consecutive b) x 256 gate-cols; 256 threads.
#define SMEM1 ((32768 + 8448 + 128 + 256 + 256 + 128) * 4)
__global__ __launch_bounds__(256, 1)
void k_pregates(const float* __restrict__ xin, const float* __restrict__ We,
                const float* __restrict__ be, int chunk) {
    extern __shared__ float sm[];
    float* sW  = sm;                 // [128][256] fp32 weights
    float* sE  = sm + 32768;         // [64][132] embeddings
    float* sX  = sE + 8448;          // [64][2]
    float* sWe = sX + 128;           // [128][2]
    float* sB  = sWe + 256;          // [256] bias slice
    float* sbe = sB + 256;           // [128]
    int tid = threadIdx.x;
    int colbase = blockIdx.y * 256;

    for (int i = tid; i < 8192; i += 256) {      // 128x256 floats as float4
        int k = i >> 6, c4 = i & 63;
        ((float4*)sW)[k * 64 + c4] =
            ((const float4*)(g_WT_ih + k * GATES + colbase))[c4];
    }
    sWe[tid] = We[tid];
    sB[tid]  = g_bias[colbase + tid];
    if (tid < 128) sbe[tid] = be[tid];

    int m0 = blockIdx.x * 64;        // m = tloc*4096 + b
    int tloc = m0 >> 12;
    int b0 = m0 & 4095;
    int tg = chunk * CHUNK + tloc;
    if (tid < 128) {
        int r = tid >> 1, cc = tid & 1;
        sX[tid] = xin[((size_t)(b0 + r) * TDIM + tg) * 2 + cc];
    }
    __syncthreads();

    for (int i = tid; i < 8192; i += 256) {      // e = relu(We x + be)
        int r = i >> 7, k = i & 127;
        float v = fmaf(sWe[2 * k], sX[2 * r],
                  fmaf(sWe[2 * k + 1], sX[2 * r + 1], sbe[k]));
        sE[r * 132 + k] = fmaxf(v, 0.f);
    }
    __syncthreads();

    int rg = tid >> 5, cg = tid & 31;
    int r0 = rg * 8, c0 = cg * 8;
    ull acc[8][4];
    #pragma unroll
    for (int p = 0; p < 4; p++) {
        ull bp = pk(sB[c0 + 2 * p], sB[c0 + 2 * p + 1]);
        #pragma unroll
        for (int rl = 0; rl < 8; rl++) acc[rl][p] = bp;
    }

    for (int k4 = 0; k4 < 128; k4 += 4) {
        float ev[8][4];
        #pragma unroll
        for (int rl = 0; rl < 8; rl++) {
            float4 t = *(const float4*)&sE[(r0 + rl) * 132 + k4];
            ev[rl][0] = t.x; ev[rl][1] = t.y; ev[rl][2] = t.z; ev[rl][3] = t.w;
        }
        #pragma unroll
        for (int kk = 0; kk < 4; kk++) {
            const float* wr = &sW[(k4 + kk) * 256 + c0];
            float4 wa = *(const float4*)wr;
            float4 wb = *(const float4*)(wr + 4);
            ull w0 = pk(wa.x, wa.y), w1 = pk(wa.z, wa.w);
            ull w2 = pk(wb.x, wb.y), w3 = pk(wb.z, wb.w);
            #pragma unroll
            for (int rl = 0; rl < 8; rl++) {
                ull ee = pk(ev[rl][kk], ev[rl][kk]);
                fma2(acc[rl][0], ee, w0);
                fma2(acc[rl][1], ee, w1);
                fma2(acc[rl][2], ee, w2);
                fma2(acc[rl][3], ee, w3);
            }
        }
    }
    #pragma unroll
    for (int rl = 0; rl < 8; rl++) {
        size_t base = (size_t)(m0 + r0 + rl) * GATES + colbase + c0;
        #pragma unroll
        for (int p = 0; p < 4; p++)
            *(ull*)(g_pre + base + 2 * p) = acc[rl][p];
    }
}

// ---------- phase 2: recurrence over one chunk ------------------------------
// CTA = 32 batch rows; thread = 8 rows x 8 g'-cols (= 2 cells). 256 threads.
#define SMEM2 (131072 + (4224 + 640 + 8) * 4)
__global__ __launch_bounds__(256, 1)
void k_recur(const float* __restrict__ Wo, const float* __restrict__ bo,
             float* __restrict__ out, int chunk) {
    extern __shared__ char smraw[];
    __half* sWh = (__half*)smraw;                 // [128][512] fp16 = 128KB
    float* sH   = (float*)(smraw + 131072);       // [32][132]
    float* sWo  = sH + 4224;                      // [5][128]
    float* sbo  = sWo + 640;                      // [5]
    int tid = threadIdx.x;
    int b0 = blockIdx.x * 32;

    for (int i = tid; i < 8192; i += 256)
        ((uint4*)sWh)[i] = ((const uint4*)g_Whh_h)[i];
    for (int i = tid; i < 4096; i += 256) {
        int r = i >> 7, k = i & 127;
        sH[r * 132 + k] = g_h[(b0 + r) * 128 + k];
    }
    for (int i = tid; i < 640; i += 256) sWo[i] = Wo[i];
    if (tid < 5) sbo[tid] = bo[tid];

    int rg = tid >> 6, cg = tid & 63;             // 4 row-groups x 64 col-groups
    int r0 = rg * 8, j0 = cg * 2;
    float creg[8][2];
    #pragma unroll
    for (int rl = 0; rl < 8; rl++) {
        creg[rl][0] = g_c[(b0 + r0 + rl) * 128 + j0];
        creg[rl][1] = g_c[(b0 + r0 + rl) * 128 + j0 + 1];
    }
    int yr = tid / 5, yd = tid - yr * 5;          // y-thread mapping (tid<160)
    __syncthreads();

    for (int tloc = 0; tloc < CHUNK; tloc++) {
        ull acc[8][4];
        #pragma unroll
        for (int rl = 0; rl < 8; rl++) {
            const ulonglong2* pp = (const ulonglong2*)
                (g_pre + ((size_t)tloc * 4096 + b0 + r0 + rl) * GATES + cg * 8);
            ulonglong2 a = pp[0], b = pp[1];
            acc[rl][0] = a.x; acc[rl][1] = a.y; acc[rl][2] = b.x; acc[rl][3] = b.y;
        }
        for (int k4 = 0; k4 < 128; k4 += 4) {
            float hv[8][4];
            #pragma unroll
            for (int rl = 0; rl < 8; rl++) {
                float4 t = *(const float4*)&sH[(r0 + rl) * 132 + k4];
                hv[rl][0] = t.x; hv[rl][1] = t.y; hv[rl][2] = t.z; hv[rl][3] = t.w;
            }
            #pragma unroll
            for (int kk = 0; kk < 4; kk++) {
                uint4 wv = *(const uint4*)&sWh[(k4 + kk) * GATES + cg * 8];
                const __half2* h2 = (const __half2*)&wv;
                float2 f0 = __half22float2(h2[0]);
                float2 f1 = __half22float2(h2[1]);
                float2 f2 = __half22float2(h2[2]);
                float2 f3 = __half22float2(h2[3]);
                ull w0 = pk(f0.x, f0.y), w1 = pk(f1.x, f1.y);
                ull w2 = pk(f2.x, f2.y), w3 = pk(f3.x, f3.y);
                #pragma unroll
                for (int rl = 0; rl < 8; rl++) {
                    ull ee = pk(hv[rl][kk], hv[rl][kk]);
                    fma2(acc[rl][0], ee, w0);
                    fma2(acc[rl][1], ee, w1);
                    fma2(acc[rl][2], ee, w2);
                    fma2(acc[rl][3], ee, w3);
                }
            }
        }
        // activations + cell update (thread-local: cols = 2 complete cells)
        float hnew[8][2];
        #pragma unroll
        for (int rl = 0; rl < 8; rl++) {
            #pragma unroll
            for (int jj = 0; jj < 2; jj++) {
                float2 a0 = upk(acc[rl][2 * jj]);      // (i, f)
                float2 a1 = upk(acc[rl][2 * jj + 1]);  // (g, o)
                float iv = sigf(a0.x), fv = sigf(a0.y);
                float gv = tanhfast(a1.x), ov = sigf(a1.y);
                float cv = fmaf(fv, creg[rl][jj], iv * gv);
                creg[rl][jj] = cv;
                hnew[rl][jj] = ov * tanhfast(cv);
            }
        }
        __syncthreads();   // all reads of old sH complete
        #pragma unroll
        for (int rl = 0; rl < 8; rl++) {
            sH[(r0 + rl) * 132 + j0]     = hnew[rl][0];
            sH[(r0 + rl) * 132 + j0 + 1] = hnew[rl][1];
        }
        __syncthreads();   // new sH visible
        // y = h_new @ Wo^T + bo
        if (tid < 160) {
            float s0 = 0.f, s1 = 0.f, s2 = 0.f, s3 = 0.f;
            #pragma unroll 4
            for (int k = 0; k < 128; k += 4) {
                float4 hh = *(const float4*)&sH[yr * 132 + k];
                float4 ww = *(const float4*)&sWo[yd * 128 + k];
                s0 = fmaf(hh.x, ww.x, s0);
                s1 = fmaf(hh.y, ww.y, s1);
                s2 = fmaf(hh.z, ww.z, s2);
                s3 = fmaf(hh.w, ww.w, s3);
            }
            float y = sbo[yd] + ((s0 + s1) + (s2 + s3));
            int tg = chunk * CHUNK + tloc;
            out[((size_t)(b0 + yr) * TDIM + tg) * 5 + yd] = y;
        }
    }

    // persist state across chunks
    for (int i = tid; i < 4096; i += 256) {
        int r = i >> 7, k = i & 127;
        g_h[(b0 + r) * 128 + k] = sH[r * 132 + k];
    }
    #pragma unroll
    for (int rl = 0; rl < 8; rl++) {
        g_c[(b0 + r0 + rl) * 128 + j0]     = creg[rl][0];
        g_c[(b0 + r0 + rl) * 128 + j0 + 1] = creg[rl][1];
    }
    if (chunk == NCH - 1) {  // final h, c outputs
        float* out_h = out + (size_t)BATCH * TDIM * 5;
        float* out_c = out_h + (size_t)BATCH * 128;
        for (int i = tid; i < 4096; i += 256) {
            int r = i >> 7, k = i & 127;
            out_h[(b0 + r) * 128 + k] = sH[r * 132 + k];
        }
        #pragma unroll
        for (int rl = 0; rl < 8; rl++) {
            out_c[(b0 + r0 + rl) * 128 + j0]     = creg[rl][0];
            out_c[(b0 + r0 + rl) * 128 + j0 + 1] = creg[rl][1];
        }
    }
}

// ---------------------------------------------------------------------------
extern "C" void kernel_launch(void* const* d_in, const int* in_sizes, int n_in,
                              void* d_out, int out_size) {
    const float* xin = (const float*)d_in[0];
    const float* We  = (const float*)d_in[1];
    const float* be  = (const float*)d_in[2];
    const float* Wih = (const float*)d_in[3];
    const float* Whh = (const float*)d_in[4];
    const float* bih = (const float*)d_in[5];
    const float* bhh = (const float*)d_in[6];
    const float* Wo  = (const float*)d_in[7];
    const float* bo  = (const float*)d_in[8];
    float* out = (float*)d_out;

    cudaFuncSetAttribute(k_pregates, cudaFuncAttributeMaxDynamicSharedMemorySize, SMEM1);
    cudaFuncSetAttribute(k_recur,    cudaFuncAttributeMaxDynamicSharedMemorySize, SMEM2);

    k_prep<<<256, 256>>>(Wih, Whh, bih, bhh);
    k_zero<<<2048, 256>>>();
    for (int c = 0; c < NCH; c++) {
        k_pregates<<<dim3(8192, 2), 256, SMEM1>>>(xin, We, be, c);
        k_recur<<<128, 256, SMEM2>>>(Wo, bo, out, c);
    }
}

// round 9
// speedup vs baseline: 1.9961x; 1.9961x over previous
#include <cuda_runtime.h>
#include <cuda_fp16.h>
#include <cstdint>

#define BATCH 4096
#define TDIM  1024
#define GATES 512
#define CHUNK 128
#define NCH   8

// ---------- device scratch --------------------------------------------------
__device__ float  g_pre[(size_t)BATCH * CHUNK * GATES];  // 1 GB staging (per chunk)
__device__ __half g_Bih[GATES * 128];                    // W_ih reordered [n][k] fp16
__device__ __half g_Bhh[GATES * 128];                    // W_hh reordered [n][k] fp16
__device__ float  g_bias[GATES];                         // b_ih+b_hh, reordered
__device__ float  g_h[BATCH * 128];
__device__ float  g_c[BATCH * 128];

// ---------- helpers ---------------------------------------------------------
__device__ __forceinline__ uint32_t smem_u32(const void* p) {
    uint32_t a;
    asm("{ .reg .u64 t; cvta.to.shared.u64 t, %1; cvt.u32.u64 %0, t; }" : "=r"(a) : "l"(p));
    return a;
}
__device__ __forceinline__ void ldm_x4(uint32_t* r, uint32_t addr) {
    asm volatile("ldmatrix.sync.aligned.m8n8.x4.shared.b16 {%0,%1,%2,%3},[%4];"
                 : "=r"(r[0]), "=r"(r[1]), "=r"(r[2]), "=r"(r[3]) : "r"(addr));
}
__device__ __forceinline__ void mma16816(float& d0, float& d1, float& d2, float& d3,
                                         uint32_t a0, uint32_t a1, uint32_t a2, uint32_t a3,
                                         uint32_t b0, uint32_t b1) {
    asm volatile("mma.sync.aligned.m16n8k16.row.col.f32.f16.f16.f32 "
                 "{%0,%1,%2,%3},{%4,%5,%6,%7},{%8,%9},{%0,%1,%2,%3};"
                 : "+f"(d0), "+f"(d1), "+f"(d2), "+f"(d3)
                 : "r"(a0), "r"(a1), "r"(a2), "r"(a3), "r"(b0), "r"(b1));
}
__device__ __forceinline__ float sigf(float x) {
    return __fdividef(1.f, 1.f + __expf(-x));
}
__device__ __forceinline__ float tanhfast(float x) {
    return 1.f - __fdividef(2.f, __expf(2.f * x) + 1.f);
}
// split x into hi (fp16) + lo (fp16 residual)
__device__ __forceinline__ void split2(float x, __half& hi, __half& lo) {
    hi = __float2half(x);
    lo = __float2half(x - __half2float(hi));
}

// row padding: 128 halves -> 272 bytes (row skew = 4 banks; conflict-free ldmatrix)
#define ROWB 272

// ---------- prep: reorder weights to [n][k], n = 4*cell + gate(i,f,g,o) -----
__global__ void k_prep(const float* __restrict__ Wih, const float* __restrict__ Whh,
                       const float* __restrict__ bih, const float* __restrict__ bhh) {
    int i = blockIdx.x * 256 + threadIdx.x;     // 512*128
    if (i >= GATES * 128) return;
    int n = i >> 7, k = i & 127;
    int go = (n & 3) * 128 + (n >> 2);          // original gate row
    g_Bih[n * 128 + k] = __float2half(Wih[go * 128 + k]);
    g_Bhh[n * 128 + k] = __float2half(Whh[go * 128 + k]);
    if (k == 0) g_bias[n] = bih[go] + bhh[go];
}

__global__ void k_zero() {
    int i = blockIdx.x * 256 + threadIdx.x;
    if (i < BATCH * 128) { g_h[i] = 0.f; g_c[i] = 0.f; }
}

// ---------- phase 1 (HMMA): pre = relu(x@We^T+be) @ Wih^T + bias ------------
// grid (128 tloc, 4 b-quarters), 256 thr (8 warps), 8 Mtiles of 128 rows each.
// e is split hi+lo fp16; gate = e_hi@W + e_lo@W in one fp32 accumulator.
#define P1_B    0                    // 512 rows x 272B = 139264
#define P1_EH   139264               // 128 x 272B = 34816
#define P1_EL   174080               // 128 x 272B = 34816
#define P1_BIAS 208896               // 512 f32
#define P1_WE   210944               // 256 f32
#define P1_BE   211968               // 128 f32
#define P1_X    212480               // 256 f32
#define SMEM_P1 213504

__global__ __launch_bounds__(256, 1)
void k_pre_tc(const float* __restrict__ xin, const float* __restrict__ We,
              const float* __restrict__ be, int chunk) {
    extern __shared__ char sm[];
    uint32_t smb = smem_u32(sm);
    float* sBias = (float*)(sm + P1_BIAS);
    float* sWe   = (float*)(sm + P1_WE);
    float* sbe   = (float*)(sm + P1_BE);
    float* sX    = (float*)(sm + P1_X);
    int tid = threadIdx.x;
    int w = tid >> 5, lane = tid & 31;
    int tloc = blockIdx.x;
    int tg = chunk * CHUNK + tloc;

    // B = W_ih [n][k] fp16 into padded rows (512 rows x 16 uint4)
    for (int idx = tid; idx < 8192; idx += 256) {
        int n = idx >> 4, kq = idx & 15;
        *(uint4*)(sm + P1_B + n * ROWB + kq * 16) = ((const uint4*)g_Bih)[idx];
    }
    for (int i = tid; i < 512; i += 256) sBias[i] = g_bias[i];
    if (tid < 256) sWe[tid] = We[tid];
    if (tid < 128) sbe[tid] = be[tid];

    int c2 = 2 * (lane & 3), r4 = lane >> 2;
    int lr = lane & 15, lh = lane >> 4;

    for (int it = 0; it < 8; it++) {
        int b0 = blockIdx.y * 1024 + it * 128;
        __syncthreads();                       // prev Mtile's tile reads done
        if (tid < 128) {
            float2 v = ((const float2*)xin)[(size_t)(b0 + tid) * TDIM + tg];
            sX[2 * tid] = v.x; sX[2 * tid + 1] = v.y;
        }
        __syncthreads();
        // e = relu(We x + be) -> split fp16 hi/lo tiles
        for (int j = 0; j < 32; j++) {
            int p = j * 256 + tid;
            int r = p >> 6, k2 = p & 63;       // k = 2*k2
            float x0 = sX[2 * r], x1 = sX[2 * r + 1];
            int k = 2 * k2;
            float e0 = fmaxf(fmaf(sWe[2 * k],     x0, fmaf(sWe[2 * k + 1], x1, sbe[k])),     0.f);
            float e1 = fmaxf(fmaf(sWe[2 * k + 2], x0, fmaf(sWe[2 * k + 3], x1, sbe[k + 1])), 0.f);
            __half h0, l0, h1, l1;
            split2(e0, h0, l0); split2(e1, h1, l1);
            *(__half2*)(sm + P1_EH + r * ROWB + k2 * 4) = __halves2half2(h0, h1);
            *(__half2*)(sm + P1_EL + r * ROWB + k2 * 4) = __halves2half2(l0, l1);
        }
        __syncthreads();

        // warp w computes rows 16w..16w+15
        uint32_t ah[8][4], al[8][4];
        uint32_t ahb = smb + P1_EH + (16 * w + lr) * ROWB + lh * 16;
        uint32_t alb = smb + P1_EL + (16 * w + lr) * ROWB + lh * 16;
        #pragma unroll
        for (int ks = 0; ks < 8; ks++) { ldm_x4(ah[ks], ahb + ks * 32); ldm_x4(al[ks], alb + ks * 32); }

        size_t grow = (size_t)tloc * 4096 + b0 + 16 * w + r4;
        #pragma unroll 2
        for (int nt = 0; nt < 64; nt++) {
            float2 bv = *(const float2*)(sBias + nt * 8 + c2);
            float d0 = bv.x, d1 = bv.y, d2 = bv.x, d3 = bv.y;
            uint32_t bbase = smb + P1_B + (nt * 8 + (lane & 7)) * ROWB + (lane >> 3) * 16;
            #pragma unroll
            for (int kp = 0; kp < 4; kp++) {
                uint32_t bf[4];
                ldm_x4(bf, bbase + kp * 64);
                mma16816(d0, d1, d2, d3, ah[2*kp][0], ah[2*kp][1], ah[2*kp][2], ah[2*kp][3], bf[0], bf[1]);
                mma16816(d0, d1, d2, d3, ah[2*kp+1][0], ah[2*kp+1][1], ah[2*kp+1][2], ah[2*kp+1][3], bf[2], bf[3]);
                mma16816(d0, d1, d2, d3, al[2*kp][0], al[2*kp][1], al[2*kp][2], al[2*kp][3], bf[0], bf[1]);
                mma16816(d0, d1, d2, d3, al[2*kp+1][0], al[2*kp+1][1], al[2*kp+1][2], al[2*kp+1][3], bf[2], bf[3]);
            }
            *(float2*)(g_pre + grow * GATES + nt * 8 + c2)       = make_float2(d0, d1);
            *(float2*)(g_pre + (grow + 8) * GATES + nt * 8 + c2) = make_float2(d2, d3);
        }
    }
}

// ---------- phase 2 (HMMA recurrence): 1 CTA = 32 batch rows ----------------
// h split hi+lo fp16; gates = pre + h_hi@W_hh + h_lo@W_hh (fp32 acc).
#define P2_B   0                     // W_hh 512 x 272B = 139264
#define P2_G   139264                // gates 32 x 516 f32 = 66048
#define P2_HH  205312                // h_hi fp16 32 x 272B = 8704
#define P2_HL  214016                // h_lo fp16 32 x 272B = 8704
#define P2_WO  222720                // 640 f32
#define P2_BO  225280                // 5 f32
#define SMEM_P2 225312
#define SGST 516                     // gate row stride (f32)

__global__ __launch_bounds__(256, 1)
void k_recur(const float* __restrict__ Wo, const float* __restrict__ bo,
             float* __restrict__ out, int chunk) {
    extern __shared__ char sm[];
    uint32_t smb = smem_u32(sm);
    float* sWo = (float*)(sm + P2_WO);
    float* sbo = (float*)(sm + P2_BO);
    int tid = threadIdx.x;
    int w = tid >> 5, lane = tid & 31;
    int b0 = blockIdx.x * 32;

    // W_hh [n][k] fp16 into padded rows
    for (int idx = tid; idx < 8192; idx += 256) {
        int n = idx >> 4, kq = idx & 15;
        *(uint4*)(sm + P2_B + n * ROWB + kq * 16) = ((const uint4*)g_Bhh)[idx];
    }
    for (int i = tid; i < 4096; i += 256) {
        int r = i >> 7, k = i & 127;
        __half hi, lo;
        split2(g_h[(b0 + r) * 128 + k], hi, lo);
        *(__half*)(sm + P2_HH + r * ROWB + k * 2) = hi;
        *(__half*)(sm + P2_HL + r * ROWB + k * 2) = lo;
    }
    for (int i = tid; i < 640; i += 256) sWo[i] = Wo[i];
    if (tid < 5) sbo[tid] = bo[tid];

    // activation ownership: row = tid/8, cells (tid%8)+8i, i=0..15
    int arow = tid >> 3, jb = tid & 7;
    float creg[16];
    #pragma unroll
    for (int i = 0; i < 16; i++)
        creg[i] = g_c[(b0 + arow) * 128 + jb + 8 * i];

    int c2 = 2 * (lane & 3), r4 = lane >> 2;
    int lr = lane & 15, lh = lane >> 4;
    int yr = tid / 5, yd = tid - yr * 5;
    __syncthreads();

    for (int tloc = 0; tloc < CHUNK; tloc++) {
        // ---- gate GEMM: warp w owns ntiles w*8..w*8+7, both mtiles ----
        #pragma unroll
        for (int mt = 0; mt < 2; mt++) {
            size_t rbase = (size_t)tloc * 4096 + b0 + mt * 16;
            float2 pa[8], pb[8];
            #pragma unroll
            for (int i = 0; i < 8; i++) {
                int col = (w * 8 + i) * 8 + c2;
                pa[i] = *(const float2*)(g_pre + (rbase + r4) * GATES + col);
                pb[i] = *(const float2*)(g_pre + (rbase + 8 + r4) * GATES + col);
            }
            uint32_t ah[8][4], al[8][4];
            uint32_t ahb = smb + P2_HH + (mt * 16 + lr) * ROWB + lh * 16;
            uint32_t alb = smb + P2_HL + (mt * 16 + lr) * ROWB + lh * 16;
            #pragma unroll
            for (int ks = 0; ks < 8; ks++) { ldm_x4(ah[ks], ahb + ks * 32); ldm_x4(al[ks], alb + ks * 32); }

            #pragma unroll
            for (int i = 0; i < 8; i++) {
                float d0 = pa[i].x, d1 = pa[i].y, d2 = pb[i].x, d3 = pb[i].y;
                uint32_t bbase = smb + P2_B + ((w * 8 + i) * 8 + (lane & 7)) * ROWB
                                 + (lane >> 3) * 16;
                #pragma unroll
                for (int kp = 0; kp < 4; kp++) {
                    uint32_t bf[4];
                    ldm_x4(bf, bbase + kp * 64);
                    mma16816(d0, d1, d2, d3, ah[2*kp][0], ah[2*kp][1], ah[2*kp][2], ah[2*kp][3], bf[0], bf[1]);
                    mma16816(d0, d1, d2, d3, ah[2*kp+1][0], ah[2*kp+1][1], ah[2*kp+1][2], ah[2*kp+1][3], bf[2], bf[3]);
                    mma16816(d0, d1, d2, d3, al[2*kp][0], al[2*kp][1], al[2*kp][2], al[2*kp][3], bf[0], bf[1]);
                    mma16816(d0, d1, d2, d3, al[2*kp+1][0], al[2*kp+1][1], al[2*kp+1][2], al[2*kp+1][3], bf[2], bf[3]);
                }
                int col = (w * 8 + i) * 8 + c2;
                *(float2*)(sm + P2_G + ((mt * 16 + r4) * SGST + col) * 4)     = make_float2(d0, d1);
                *(float2*)(sm + P2_G + ((mt * 16 + 8 + r4) * SGST + col) * 4) = make_float2(d2, d3);
            }
        }
        __syncthreads();

        // ---- activation + state update ----
        #pragma unroll 4
        for (int i = 0; i < 16; i++) {
            int cell = jb + 8 * i;
            float4 g4 = *(const float4*)(sm + P2_G + (arow * SGST + 4 * cell) * 4);
            float iv = sigf(g4.x), fv = sigf(g4.y);
            float gv = tanhfast(g4.z), ov = sigf(g4.w);
            float cc = fmaf(fv, creg[i], iv * gv);
            creg[i] = cc;
            float hh = ov * tanhfast(cc);
            __half hi, lo;
            split2(hh, hi, lo);
            *(__half*)(sm + P2_HH + arow * ROWB + cell * 2) = hi;
            *(__half*)(sm + P2_HL + arow * ROWB + cell * 2) = lo;
            if (tloc == CHUNK - 1) {
                // persist BOTH h and c across chunk boundary (R8 bug: c was dropped)
                g_h[(b0 + arow) * 128 + cell] = hh;
                g_c[(b0 + arow) * 128 + cell] = cc;
                if (chunk == NCH - 1) {
                    float* out_h = out + (size_t)BATCH * TDIM * 5;
                    float* out_c = out_h + (size_t)BATCH * 128;
                    out_h[(b0 + arow) * 128 + cell] = hh;
                    out_c[(b0 + arow) * 128 + cell] = cc;
                }
            }
        }
        __syncthreads();

        // ---- y = h_new @ Wo^T + bo (160 threads) ----
        if (tid < 160) {
            float s0 = 0.f, s1 = 0.f;
            const char* hh = sm + P2_HH + yr * ROWB;
            const char* hl = sm + P2_HL + yr * ROWB;
            const float* wrow = sWo + yd * 128;
            #pragma unroll 8
            for (int k = 0; k < 128; k += 2) {
                float2 fh = __half22float2(*(const __half2*)(hh + k * 2));
                float2 fl = __half22float2(*(const __half2*)(hl + k * 2));
                s0 = fmaf(fh.x + fl.x, wrow[k],     s0);
                s1 = fmaf(fh.y + fl.y, wrow[k + 1], s1);
            }
            int tg = chunk * CHUNK + tloc;
            out[((size_t)(b0 + yr) * TDIM + tg) * 5 + yd] = s0 + s1 + sbo[yd];
        }
    }
}

// ---------------------------------------------------------------------------
extern "C" void kernel_launch(void* const* d_in, const int* in_sizes, int n_in,
                              void* d_out, int out_size) {
    const float* xin = (const float*)d_in[0];
    const float* We  = (const float*)d_in[1];
    const float* be  = (const float*)d_in[2];
    const float* Wih = (const float*)d_in[3];
    const float* Whh = (const float*)d_in[4];
    const float* bih = (const float*)d_in[5];
    const float* bhh = (const float*)d_in[6];
    const float* Wo  = (const float*)d_in[7];
    const float* bo  = (const float*)d_in[8];
    float* out = (float*)d_out;

    cudaFuncSetAttribute(k_pre_tc, cudaFuncAttributeMaxDynamicSharedMemorySize, SMEM_P1);
    cudaFuncSetAttribute(k_recur,  cudaFuncAttributeMaxDynamicSharedMemorySize, SMEM_P2);

    k_prep<<<256, 256>>>(Wih, Whh, bih, bhh);
    k_zero<<<2048, 256>>>();
    for (int c = 0; c < NCH; c++) {
        k_pre_tc<<<dim3(128, 4), 256, SMEM_P1>>>(xin, We, be, c);
        k_recur<<<128, 256, SMEM_P2>>>(Wo, bo, out, c);
    }
}

// round 10
// speedup vs baseline: 2.1803x; 1.0923x over previous
#include <cuda_runtime.h>
#include <cuda_fp16.h>
#include <cstdint>

#define BATCH 4096
#define TDIM  1024
#define GATES 512
#define CHUNK 128
#define NCH   8

// ---------- device scratch --------------------------------------------------
__device__ float  g_pre[(size_t)BATCH * CHUNK * GATES];  // 1 GB staging (per chunk)
__device__ __half g_Bih[GATES * 128];                    // W_ih reordered [n][k] fp16
__device__ __half g_Bhh[GATES * 128];                    // W_hh reordered [n][k] fp16
__device__ float  g_bias[GATES];                         // b_ih+b_hh, reordered
__device__ float  g_h[BATCH * 128];
__device__ float  g_c[BATCH * 128];

// ---------- helpers ---------------------------------------------------------
__device__ __forceinline__ uint32_t smem_u32(const void* p) {
    uint32_t a;
    asm("{ .reg .u64 t; cvta.to.shared.u64 t, %1; cvt.u32.u64 %0, t; }" : "=r"(a) : "l"(p));
    return a;
}
__device__ __forceinline__ void ldm_x4(uint32_t* r, uint32_t addr) {
    asm volatile("ldmatrix.sync.aligned.m8n8.x4.shared.b16 {%0,%1,%2,%3},[%4];"
                 : "=r"(r[0]), "=r"(r[1]), "=r"(r[2]), "=r"(r[3]) : "r"(addr));
}
__device__ __forceinline__ void mma16816(float& d0, float& d1, float& d2, float& d3,
                                         uint32_t a0, uint32_t a1, uint32_t a2, uint32_t a3,
                                         uint32_t b0, uint32_t b1) {
    asm volatile("mma.sync.aligned.m16n8k16.row.col.f32.f16.f16.f32 "
                 "{%0,%1,%2,%3},{%4,%5,%6,%7},{%8,%9},{%0,%1,%2,%3};"
                 : "+f"(d0), "+f"(d1), "+f"(d2), "+f"(d3)
                 : "r"(a0), "r"(a1), "r"(a2), "r"(a3), "r"(b0), "r"(b1));
}
__device__ __forceinline__ float sigf(float x) {
    return __fdividef(1.f, 1.f + __expf(-x));
}
__device__ __forceinline__ float tanhfast(float x) {
    return 1.f - __fdividef(2.f, __expf(2.f * x) + 1.f);
}
// split x into hi (fp16) + lo (fp16 residual)
__device__ __forceinline__ void split2(float x, __half& hi, __half& lo) {
    hi = __float2half(x);
    lo = __float2half(x - __half2float(hi));
}

// row padding: 128 halves -> 272 bytes (row skew = 4 banks; conflict-free ldmatrix)
#define ROWB 272

// ---------- prep: reorder weights to [n][k], n = 4*cell + gate(i,f,g,o) -----
__global__ void k_prep(const float* __restrict__ Wih, const float* __restrict__ Whh,
                       const float* __restrict__ bih, const float* __restrict__ bhh) {
    int i = blockIdx.x * 256 + threadIdx.x;     // 512*128
    if (i >= GATES * 128) return;
    int n = i >> 7, k = i & 127;
    int go = (n & 3) * 128 + (n >> 2);          // original gate row
    g_Bih[n * 128 + k] = __float2half(Wih[go * 128 + k]);
    g_Bhh[n * 128 + k] = __float2half(Whh[go * 128 + k]);
    if (k == 0) g_bias[n] = bih[go] + bhh[go];
}

__global__ void k_zero() {
    int i = blockIdx.x * 256 + threadIdx.x;
    if (i < BATCH * 128) { g_h[i] = 0.f; g_c[i] = 0.f; }
}

// ---------- phase 1 (HMMA): pre = relu(x@We^T+be) @ Wih^T + bias ------------
// grid (128 tloc, 4 b-quarters), 256 thr (8 warps), 8 Mtiles of 128 rows each.
// e is split hi+lo fp16; gate = e_hi@W + e_lo@W in one fp32 accumulator.
#define P1_B    0                    // 512 rows x 272B = 139264
#define P1_EH   139264               // 128 x 272B = 34816
#define P1_EL   174080               // 128 x 272B = 34816
#define P1_BIAS 208896               // 512 f32
#define P1_WE   210944               // 256 f32
#define P1_BE   211968               // 128 f32
#define P1_X    212480               // 256 f32
#define SMEM_P1 213504

__global__ __launch_bounds__(256, 1)
void k_pre_tc(const float* __restrict__ xin, const float* __restrict__ We,
              const float* __restrict__ be, int chunk) {
    extern __shared__ char sm[];
    uint32_t smb = smem_u32(sm);
    float* sBias = (float*)(sm + P1_BIAS);
    float* sWe   = (float*)(sm + P1_WE);
    float* sbe   = (float*)(sm + P1_BE);
    float* sX    = (float*)(sm + P1_X);
    int tid = threadIdx.x;
    int w = tid >> 5, lane = tid & 31;
    int tloc = blockIdx.x;
    int tg = chunk * CHUNK + tloc;

    // B = W_ih [n][k] fp16 into padded rows (512 rows x 16 uint4)
    for (int idx = tid; idx < 8192; idx += 256) {
        int n = idx >> 4, kq = idx & 15;
        *(uint4*)(sm + P1_B + n * ROWB + kq * 16) = ((const uint4*)g_Bih)[idx];
    }
    for (int i = tid; i < 512; i += 256) sBias[i] = g_bias[i];
    if (tid < 256) sWe[tid] = We[tid];
    if (tid < 128) sbe[tid] = be[tid];

    int c2 = 2 * (lane & 3), r4 = lane >> 2;
    int lr = lane & 15, lh = lane >> 4;

    for (int it = 0; it < 8; it++) {
        int b0 = blockIdx.y * 1024 + it * 128;
        __syncthreads();                       // prev Mtile's tile reads done
        if (tid < 128) {
            float2 v = ((const float2*)xin)[(size_t)(b0 + tid) * TDIM + tg];
            sX[2 * tid] = v.x; sX[2 * tid + 1] = v.y;
        }
        __syncthreads();
        // e = relu(We x + be) -> split fp16 hi/lo tiles
        for (int j = 0; j < 32; j++) {
            int p = j * 256 + tid;
            int r = p >> 6, k2 = p & 63;       // k = 2*k2
            float x0 = sX[2 * r], x1 = sX[2 * r + 1];
            int k = 2 * k2;
            float e0 = fmaxf(fmaf(sWe[2 * k],     x0, fmaf(sWe[2 * k + 1], x1, sbe[k])),     0.f);
            float e1 = fmaxf(fmaf(sWe[2 * k + 2], x0, fmaf(sWe[2 * k + 3], x1, sbe[k + 1])), 0.f);
            __half h0, l0, h1, l1;
            split2(e0, h0, l0); split2(e1, h1, l1);
            *(__half2*)(sm + P1_EH + r * ROWB + k2 * 4) = __halves2half2(h0, h1);
            *(__half2*)(sm + P1_EL + r * ROWB + k2 * 4) = __halves2half2(l0, l1);
        }
        __syncthreads();

        // warp w computes rows 16w..16w+15
        uint32_t ah[8][4], al[8][4];
        uint32_t ahb = smb + P1_EH + (16 * w + lr) * ROWB + lh * 16;
        uint32_t alb = smb + P1_EL + (16 * w + lr) * ROWB + lh * 16;
        #pragma unroll
        for (int ks = 0; ks < 8; ks++) { ldm_x4(ah[ks], ahb + ks * 32); ldm_x4(al[ks], alb + ks * 32); }

        size_t grow = (size_t)tloc * 4096 + b0 + 16 * w + r4;
        #pragma unroll 2
        for (int nt = 0; nt < 64; nt++) {
            float2 bv = *(const float2*)(sBias + nt * 8 + c2);
            float d0 = bv.x, d1 = bv.y, d2 = bv.x, d3 = bv.y;
            uint32_t bbase = smb + P1_B + (nt * 8 + (lane & 7)) * ROWB + (lane >> 3) * 16;
            #pragma unroll
            for (int kp = 0; kp < 4; kp++) {
                uint32_t bf[4];
                ldm_x4(bf, bbase + kp * 64);
                mma16816(d0, d1, d2, d3, ah[2*kp][0], ah[2*kp][1], ah[2*kp][2], ah[2*kp][3], bf[0], bf[1]);
                mma16816(d0, d1, d2, d3, ah[2*kp+1][0], ah[2*kp+1][1], ah[2*kp+1][2], ah[2*kp+1][3], bf[2], bf[3]);
                mma16816(d0, d1, d2, d3, al[2*kp][0], al[2*kp][1], al[2*kp][2], al[2*kp][3], bf[0], bf[1]);
                mma16816(d0, d1, d2, d3, al[2*kp+1][0], al[2*kp+1][1], al[2*kp+1][2], al[2*kp+1][3], bf[2], bf[3]);
            }
            *(float2*)(g_pre + grow * GATES + nt * 8 + c2)       = make_float2(d0, d1);
            *(float2*)(g_pre + (grow + 8) * GATES + nt * 8 + c2) = make_float2(d2, d3);
        }
    }
}

// ---------- phase 2 (HMMA recurrence): 1 CTA = 32 batch rows ----------------
// h split hi+lo fp16; gates = pre + h_hi@W_hh + h_lo@W_hh (fp32 acc).
// g_pre acc-init is register double-buffered: loads for step t+1 issue right
// after step t's GEMM, hiding DRAM latency behind activation + barriers.
#define P2_B   0                     // W_hh 512 x 272B = 139264
#define P2_G   139264                // gates 32 x 516 f32 = 66048
#define P2_HH  205312                // h_hi fp16 32 x 272B = 8704
#define P2_HL  214016                // h_lo fp16 32 x 272B = 8704
#define P2_WO  222720                // 640 f32
#define P2_BO  225280                // 5 f32
#define SMEM_P2 225312
#define SGST 516                     // gate row stride (f32)

__global__ __launch_bounds__(256, 1)
void k_recur(const float* __restrict__ Wo, const float* __restrict__ bo,
             float* __restrict__ out, int chunk) {
    extern __shared__ char sm[];
    uint32_t smb = smem_u32(sm);
    float* sWo = (float*)(sm + P2_WO);
    float* sbo = (float*)(sm + P2_BO);
    int tid = threadIdx.x;
    int w = tid >> 5, lane = tid & 31;
    int b0 = blockIdx.x * 32;

    // W_hh [n][k] fp16 into padded rows
    for (int idx = tid; idx < 8192; idx += 256) {
        int n = idx >> 4, kq = idx & 15;
        *(uint4*)(sm + P2_B + n * ROWB + kq * 16) = ((const uint4*)g_Bhh)[idx];
    }
    for (int i = tid; i < 4096; i += 256) {
        int r = i >> 7, k = i & 127;
        __half hi, lo;
        split2(g_h[(b0 + r) * 128 + k], hi, lo);
        *(__half*)(sm + P2_HH + r * ROWB + k * 2) = hi;
        *(__half*)(sm + P2_HL + r * ROWB + k * 2) = lo;
    }
    for (int i = tid; i < 640; i += 256) sWo[i] = Wo[i];
    if (tid < 5) sbo[tid] = bo[tid];

    // activation ownership: row = tid/8, cells (tid%8)+8i, i=0..15
    int arow = tid >> 3, jb = tid & 7;
    float creg[16];
    #pragma unroll
    for (int i = 0; i < 16; i++)
        creg[i] = g_c[(b0 + arow) * 128 + jb + 8 * i];

    int c2 = 2 * (lane & 3), r4 = lane >> 2;
    int lr = lane & 15, lh = lane >> 4;
    int yr = tid / 5, yd = tid - yr * 5;
    __syncthreads();

    // register double-buffer for g_pre acc-init (prefetch step 0)
    float2 pa[2][8], pb[2][8];
    #pragma unroll
    for (int mt = 0; mt < 2; mt++) {
        size_t rbase = (size_t)(b0 + mt * 16);
        #pragma unroll
        for (int i = 0; i < 8; i++) {
            int col = (w * 8 + i) * 8 + c2;
            pa[mt][i] = *(const float2*)(g_pre + (rbase + r4) * GATES + col);
            pb[mt][i] = *(const float2*)(g_pre + (rbase + 8 + r4) * GATES + col);
        }
    }

    for (int tloc = 0; tloc < CHUNK; tloc++) {
        // ---- gate GEMM: warp w owns ntiles w*8..w*8+7, both mtiles ----
        #pragma unroll
        for (int mt = 0; mt < 2; mt++) {
            uint32_t ah[8][4], al[8][4];
            uint32_t ahb = smb + P2_HH + (mt * 16 + lr) * ROWB + lh * 16;
            uint32_t alb = smb + P2_HL + (mt * 16 + lr) * ROWB + lh * 16;
            #pragma unroll
            for (int ks = 0; ks < 8; ks++) { ldm_x4(ah[ks], ahb + ks * 32); ldm_x4(al[ks], alb + ks * 32); }

            #pragma unroll
            for (int i = 0; i < 8; i++) {
                float d0 = pa[mt][i].x, d1 = pa[mt][i].y, d2 = pb[mt][i].x, d3 = pb[mt][i].y;
                uint32_t bbase = smb + P2_B + ((w * 8 + i) * 8 + (lane & 7)) * ROWB
                                 + (lane >> 3) * 16;
                #pragma unroll
                for (int kp = 0; kp < 4; kp++) {
                    uint32_t bf[4];
                    ldm_x4(bf, bbase + kp * 64);
                    mma16816(d0, d1, d2, d3, ah[2*kp][0], ah[2*kp][1], ah[2*kp][2], ah[2*kp][3], bf[0], bf[1]);
                    mma16816(d0, d1, d2, d3, ah[2*kp+1][0], ah[2*kp+1][1], ah[2*kp+1][2], ah[2*kp+1][3], bf[2], bf[3]);
                    mma16816(d0, d1, d2, d3, al[2*kp][0], al[2*kp][1], al[2*kp][2], al[2*kp][3], bf[0], bf[1]);
                    mma16816(d0, d1, d2, d3, al[2*kp+1][0], al[2*kp+1][1], al[2*kp+1][2], al[2*kp+1][3], bf[2], bf[3]);
                }
                int col = (w * 8 + i) * 8 + c2;
                *(float2*)(sm + P2_G + ((mt * 16 + r4) * SGST + col) * 4)     = make_float2(d0, d1);
                *(float2*)(sm + P2_G + ((mt * 16 + 8 + r4) * SGST + col) * 4) = make_float2(d2, d3);
            }
        }

        // ---- prefetch next step's acc-init (hidden under act + barriers) ----
        if (tloc + 1 < CHUNK) {
            #pragma unroll
            for (int mt = 0; mt < 2; mt++) {
                size_t rbase = (size_t)(tloc + 1) * 4096 + b0 + mt * 16;
                #pragma unroll
                for (int i = 0; i < 8; i++) {
                    int col = (w * 8 + i) * 8 + c2;
                    pa[mt][i] = *(const float2*)(g_pre + (rbase + r4) * GATES + col);
                    pb[mt][i] = *(const float2*)(g_pre + (rbase + 8 + r4) * GATES + col);
                }
            }
        }
        __syncthreads();

        // ---- activation + state update ----
        #pragma unroll 4
        for (int i = 0; i < 16; i++) {
            int cell = jb + 8 * i;
            float4 g4 = *(const float4*)(sm + P2_G + (arow * SGST + 4 * cell) * 4);
            float iv = sigf(g4.x), fv = sigf(g4.y);
            float gv = tanhfast(g4.z), ov = sigf(g4.w);
            float cc = fmaf(fv, creg[i], iv * gv);
            creg[i] = cc;
            float hh = ov * tanhfast(cc);
            __half hi, lo;
            split2(hh, hi, lo);
            *(__half*)(sm + P2_HH + arow * ROWB + cell * 2) = hi;
            *(__half*)(sm + P2_HL + arow * ROWB + cell * 2) = lo;
            if (tloc == CHUNK - 1) {
                // persist BOTH h and c across chunk boundary
                g_h[(b0 + arow) * 128 + cell] = hh;
                g_c[(b0 + arow) * 128 + cell] = cc;
                if (chunk == NCH - 1) {
                    float* out_h = out + (size_t)BATCH * TDIM * 5;
                    float* out_c = out_h + (size_t)BATCH * 128;
                    out_h[(b0 + arow) * 128 + cell] = hh;
                    out_c[(b0 + arow) * 128 + cell] = cc;
                }
            }
        }
        __syncthreads();

        // ---- y = h_new @ Wo^T + bo (160 threads) ----
        if (tid < 160) {
            float s0 = 0.f, s1 = 0.f;
            const char* hh = sm + P2_HH + yr * ROWB;
            const char* hl = sm + P2_HL + yr * ROWB;
            const float* wrow = sWo + yd * 128;
            #pragma unroll 8
            for (int k = 0; k < 128; k += 2) {
                float2 fh = __half22float2(*(const __half2*)(hh + k * 2));
                float2 fl = __half22float2(*(const __half2*)(hl + k * 2));
                s0 = fmaf(fh.x + fl.x, wrow[k],     s0);
                s1 = fmaf(fh.y + fl.y, wrow[k + 1], s1);
            }
            int tg = chunk * CHUNK + tloc;
            out[((size_t)(b0 + yr) * TDIM + tg) * 5 + yd] = s0 + s1 + sbo[yd];
        }
    }
}

// ---------------------------------------------------------------------------
extern "C" void kernel_launch(void* const* d_in, const int* in_sizes, int n_in,
                              void* d_out, int out_size) {
    const float* xin = (const float*)d_in[0];
    const float* We  = (const float*)d_in[1];
    const float* be  = (const float*)d_in[2];
    const float* Wih = (const float*)d_in[3];
    const float* Whh = (const float*)d_in[4];
    const float* bih = (const float*)d_in[5];
    const float* bhh = (const float*)d_in[6];
    const float* Wo  = (const float*)d_in[7];
    const float* bo  = (const float*)d_in[8];
    float* out = (float*)d_out;

    cudaFuncSetAttribute(k_pre_tc, cudaFuncAttributeMaxDynamicSharedMemorySize, SMEM_P1);
    cudaFuncSetAttribute(k_recur,  cudaFuncAttributeMaxDynamicSharedMemorySize, SMEM_P2);

    k_prep<<<256, 256>>>(Wih, Whh, bih, bhh);
    k_zero<<<2048, 256>>>();
    for (int c = 0; c < NCH; c++) {
        k_pre_tc<<<dim3(128, 4), 256, SMEM_P1>>>(xin, We, be, c);
        k_recur<<<128, 256, SMEM_P2>>>(Wo, bo, out, c);
    }
}

// round 13
// speedup vs baseline: 2.4934x; 1.1436x over previous
#include <cuda_runtime.h>
#include <cuda_fp16.h>
#include <cstdint>

#define BATCH 4096
#define TDIM  1024
#define GATES 512
#define CHUNK 128
#define NCH   8

// ---------- device scratch --------------------------------------------------
__device__ float  g_pre[(size_t)BATCH * CHUNK * GATES];  // 1 GB staging (per chunk)
__device__ __half g_Bih[GATES * 128];                    // W_ih reordered [n][k] fp16
__device__ __half g_Bhh[GATES * 128];                    // W_hh reordered [n][k] fp16
__device__ float  g_bias[GATES];                         // b_ih+b_hh, reordered
__device__ float  g_h[BATCH * 128];
__device__ float  g_c[BATCH * 128];

// ---------- helpers ---------------------------------------------------------
__device__ __forceinline__ uint32_t smem_u32(const void* p) {
    uint32_t a;
    asm("{ .reg .u64 t; cvta.to.shared.u64 t, %1; cvt.u32.u64 %0, t; }" : "=r"(a) : "l"(p));
    return a;
}
__device__ __forceinline__ void ldm_x4(uint32_t* r, uint32_t addr) {
    asm volatile("ldmatrix.sync.aligned.m8n8.x4.shared.b16 {%0,%1,%2,%3},[%4];"
                 : "=r"(r[0]), "=r"(r[1]), "=r"(r[2]), "=r"(r[3]) : "r"(addr));
}
__device__ __forceinline__ void mma16816(float& d0, float& d1, float& d2, float& d3,
                                         uint32_t a0, uint32_t a1, uint32_t a2, uint32_t a3,
                                         uint32_t b0, uint32_t b1) {
    asm volatile("mma.sync.aligned.m16n8k16.row.col.f32.f16.f16.f32 "
                 "{%0,%1,%2,%3},{%4,%5,%6,%7},{%8,%9},{%0,%1,%2,%3};"
                 : "+f"(d0), "+f"(d1), "+f"(d2), "+f"(d3)
                 : "r"(a0), "r"(a1), "r"(a2), "r"(a3), "r"(b0), "r"(b1));
}
__device__ __forceinline__ float sigf(float x) {
    return __fdividef(1.f, 1.f + __expf(-x));
}
__device__ __forceinline__ float tanhfast(float x) {
    return 1.f - __fdividef(2.f, __expf(2.f * x) + 1.f);
}
// split x into hi (fp16) + lo (fp16 residual)
__device__ __forceinline__ void split2(float x, __half& hi, __half& lo) {
    hi = __float2half(x);
    lo = __float2half(x - __half2float(hi));
}

// row padding: 128 halves -> 272 bytes (row skew = 4 banks; conflict-free ldmatrix)
#define ROWB 272

// ---------- prep: reorder weights to [n][k], n = 4*cell + gate(i,f,g,o) -----
__global__ void k_prep(const float* __restrict__ Wih, const float* __restrict__ Whh,
                       const float* __restrict__ bih, const float* __restrict__ bhh) {
    int i = blockIdx.x * 256 + threadIdx.x;     // 512*128
    if (i >= GATES * 128) return;
    int n = i >> 7, k = i & 127;
    int go = (n & 3) * 128 + (n >> 2);          // original gate row
    g_Bih[n * 128 + k] = __float2half(Wih[go * 128 + k]);
    g_Bhh[n * 128 + k] = __float2half(Whh[go * 128 + k]);
    if (k == 0) g_bias[n] = bih[go] + bhh[go];
}

__global__ void k_zero() {
    int i = blockIdx.x * 256 + threadIdx.x;
    if (i < BATCH * 128) { g_h[i] = 0.f; g_c[i] = 0.f; }
}

// ---------- phase 1 (HMMA): pre = relu(x@We^T+be) @ Wih^T + bias ------------
// grid (128 tloc, 4 b-quarters), 256 thr (8 warps), 8 Mtiles of 128 rows each.
// e is split hi+lo fp16; gate = e_hi@W + e_lo@W in one fp32 accumulator.
#define P1_B    0                    // 512 rows x 272B = 139264
#define P1_EH   139264               // 128 x 272B = 34816
#define P1_EL   174080               // 128 x 272B = 34816
#define P1_BIAS 208896               // 512 f32
#define P1_WE   210944               // 256 f32
#define P1_BE   211968               // 128 f32
#define P1_X    212480               // 256 f32
#define SMEM_P1 213504

__global__ __launch_bounds__(256, 1)
void k_pre_tc(const float* __restrict__ xin, const float* __restrict__ We,
              const float* __restrict__ be, int chunk) {
    extern __shared__ char sm[];
    uint32_t smb = smem_u32(sm);
    float* sBias = (float*)(sm + P1_BIAS);
    float* sWe   = (float*)(sm + P1_WE);
    float* sbe   = (float*)(sm + P1_BE);
    float* sX    = (float*)(sm + P1_X);
    int tid = threadIdx.x;
    int w = tid >> 5, lane = tid & 31;
    int tloc = blockIdx.x;
    int tg = chunk * CHUNK + tloc;

    // B = W_ih [n][k] fp16 into padded rows (512 rows x 16 uint4)
    for (int idx = tid; idx < 8192; idx += 256) {
        int n = idx >> 4, kq = idx & 15;
        *(uint4*)(sm + P1_B + n * ROWB + kq * 16) = ((const uint4*)g_Bih)[idx];
    }
    for (int i = tid; i < 512; i += 256) sBias[i] = g_bias[i];
    if (tid < 256) sWe[tid] = We[tid];
    if (tid < 128) sbe[tid] = be[tid];

    int c2 = 2 * (lane & 3), r4 = lane >> 2;
    int lr = lane & 15, lh = lane >> 4;

    for (int it = 0; it < 8; it++) {
        int b0 = blockIdx.y * 1024 + it * 128;
        __syncthreads();                       // prev Mtile's tile reads done
        if (tid < 128) {
            float2 v = ((const float2*)xin)[(size_t)(b0 + tid) * TDIM + tg];
            sX[2 * tid] = v.x; sX[2 * tid + 1] = v.y;
        }
        __syncthreads();
        // e = relu(We x + be) -> split fp16 hi/lo tiles
        for (int j = 0; j < 32; j++) {
            int p = j * 256 + tid;
            int r = p >> 6, k2 = p & 63;       // k = 2*k2
            float x0 = sX[2 * r], x1 = sX[2 * r + 1];
            int k = 2 * k2;
            float e0 = fmaxf(fmaf(sWe[2 * k],     x0, fmaf(sWe[2 * k + 1], x1, sbe[k])),     0.f);
            float e1 = fmaxf(fmaf(sWe[2 * k + 2], x0, fmaf(sWe[2 * k + 3], x1, sbe[k + 1])), 0.f);
            __half h0, l0, h1, l1;
            split2(e0, h0, l0); split2(e1, h1, l1);
            *(__half2*)(sm + P1_EH + r * ROWB + k2 * 4) = __halves2half2(h0, h1);
            *(__half2*)(sm + P1_EL + r * ROWB + k2 * 4) = __halves2half2(l0, l1);
        }
        __syncthreads();

        // warp w computes rows 16w..16w+15
        uint32_t ah[8][4], al[8][4];
        uint32_t ahb = smb + P1_EH + (16 * w + lr) * ROWB + lh * 16;
        uint32_t alb = smb + P1_EL + (16 * w + lr) * ROWB + lh * 16;
        #pragma unroll
        for (int ks = 0; ks < 8; ks++) { ldm_x4(ah[ks], ahb + ks * 32); ldm_x4(al[ks], alb + ks * 32); }

        size_t grow = (size_t)tloc * 4096 + b0 + 16 * w + r4;
        #pragma unroll 2
        for (int nt = 0; nt < 64; nt++) {
            float2 bv = *(const float2*)(sBias + nt * 8 + c2);
            float d0 = bv.x, d1 = bv.y, d2 = bv.x, d3 = bv.y;
            uint32_t bbase = smb + P1_B + (nt * 8 + (lane & 7)) * ROWB + (lane >> 3) * 16;
            #pragma unroll
            for (int kp = 0; kp < 4; kp++) {
                uint32_t bf[4];
                ldm_x4(bf, bbase + kp * 64);
                mma16816(d0, d1, d2, d3, ah[2*kp][0], ah[2*kp][1], ah[2*kp][2], ah[2*kp][3], bf[0], bf[1]);
                mma16816(d0, d1, d2, d3, ah[2*kp+1][0], ah[2*kp+1][1], ah[2*kp+1][2], ah[2*kp+1][3], bf[2], bf[3]);
                mma16816(d0, d1, d2, d3, al[2*kp][0], al[2*kp][1], al[2*kp][2], al[2*kp][3], bf[0], bf[1]);
                mma16816(d0, d1, d2, d3, al[2*kp+1][0], al[2*kp+1][1], al[2*kp+1][2], al[2*kp+1][3], bf[2], bf[3]);
            }
            *(float2*)(g_pre + grow * GATES + nt * 8 + c2)       = make_float2(d0, d1);
            *(float2*)(g_pre + (grow + 8) * GATES + nt * 8 + c2) = make_float2(d2, d3);
        }
    }
}

// ---------- phase 2 (HMMA recurrence): 1 CTA = 32 batch rows, 512 threads ---
// 16 warps: mt = w>>3 (m-tile), wn = w&7 owns ntiles wn*8..wn*8+7 of that mt.
// h split hi+lo fp16; gates = pre + h_hi@W_hh + h_lo@W_hh (fp32 acc).
// g_pre acc-init register double-buffered across steps.
#define P2_B   0                     // W_hh 512 x 272B = 139264
#define P2_G   139264                // gates 32 x 516 f32 = 66048
#define P2_HH  205312                // h_hi fp16 32 x 272B = 8704
#define P2_HL  214016                // h_lo fp16 32 x 272B = 8704
#define P2_WO  222720                // 640 f32
#define P2_BO  225280                // 5 f32
#define SMEM_P2 225312
#define SGST 516                     // gate row stride (f32)

__global__ __launch_bounds__(512, 1)
void k_recur(const float* __restrict__ Wo, const float* __restrict__ bo,
             float* __restrict__ out, int chunk) {
    extern __shared__ char sm[];
    uint32_t smb = smem_u32(sm);
    float* sWo = (float*)(sm + P2_WO);
    float* sbo = (float*)(sm + P2_BO);
    int tid = threadIdx.x;
    int w = tid >> 5, lane = tid & 31;
    int mt = w >> 3, wn = w & 7;
    int b0 = blockIdx.x * 32;

    // W_hh [n][k] fp16 into padded rows
    for (int idx = tid; idx < 8192; idx += 512) {
        int n = idx >> 4, kq = idx & 15;
        *(uint4*)(sm + P2_B + n * ROWB + kq * 16) = ((const uint4*)g_Bhh)[idx];
    }
    for (int i = tid; i < 4096; i += 512) {
        int r = i >> 7, k = i & 127;
        __half hi, lo;
        split2(g_h[(b0 + r) * 128 + k], hi, lo);
        *(__half*)(sm + P2_HH + r * ROWB + k * 2) = hi;
        *(__half*)(sm + P2_HL + r * ROWB + k * 2) = lo;
    }
    for (int i = tid; i < 640; i += 512) sWo[i] = Wo[i];
    if (tid < 5) sbo[tid] = bo[tid];

    // activation ownership: row = tid/16, cells (tid%16)+16i, i=0..7
    int arow = tid >> 4, jb = tid & 15;
    float creg[8];
    #pragma unroll
    for (int i = 0; i < 8; i++)
        creg[i] = g_c[(b0 + arow) * 128 + jb + 16 * i];

    int c2 = 2 * (lane & 3), r4 = lane >> 2;
    int lr = lane & 15, lh = lane >> 4;
    int yr = tid / 5, yd = tid - yr * 5;
    __syncthreads();

    // register double-buffer for g_pre acc-init (prefetch step 0)
    float2 pa[8], pb[8];
    {
        size_t rbase = (size_t)(b0 + mt * 16);
        #pragma unroll
        for (int i = 0; i < 8; i++) {
            int col = (wn * 8 + i) * 8 + c2;
            pa[i] = *(const float2*)(g_pre + (rbase + r4) * GATES + col);
            pb[i] = *(const float2*)(g_pre + (rbase + 8 + r4) * GATES + col);
        }
    }

    for (int tloc = 0; tloc < CHUNK; tloc++) {
        // ---- gate GEMM: warp (mt, wn) owns ntiles wn*8..wn*8+7 of mtile mt --
        uint32_t ah[8][4], al[8][4];
        uint32_t ahb = smb + P2_HH + (mt * 16 + lr) * ROWB + lh * 16;
        uint32_t alb = smb + P2_HL + (mt * 16 + lr) * ROWB + lh * 16;
        #pragma unroll
        for (int ks = 0; ks < 8; ks++) { ldm_x4(ah[ks], ahb + ks * 32); ldm_x4(al[ks], alb + ks * 32); }

        #pragma unroll
        for (int i = 0; i < 8; i++) {
            float d0 = pa[i].x, d1 = pa[i].y, d2 = pb[i].x, d3 = pb[i].y;
            uint32_t bbase = smb + P2_B + ((wn * 8 + i) * 8 + (lane & 7)) * ROWB
                             + (lane >> 3) * 16;
            #pragma unroll
            for (int kp = 0; kp < 4; kp++) {
                uint32_t bf[4];
                ldm_x4(bf, bbase + kp * 64);
                mma16816(d0, d1, d2, d3, ah[2*kp][0], ah[2*kp][1], ah[2*kp][2], ah[2*kp][3], bf[0], bf[1]);
                mma16816(d0, d1, d2, d3, ah[2*kp+1][0], ah[2*kp+1][1], ah[2*kp+1][2], ah[2*kp+1][3], bf[2], bf[3]);
                mma16816(d0, d1, d2, d3, al[2*kp][0], al[2*kp][1], al[2*kp][2], al[2*kp][3], bf[0], bf[1]);
                mma16816(d0, d1, d2, d3, al[2*kp+1][0], al[2*kp+1][1], al[2*kp+1][2], al[2*kp+1][3], bf[2], bf[3]);
            }
            int col = (wn * 8 + i) * 8 + c2;
            *(float2*)(sm + P2_G + ((mt * 16 + r4) * SGST + col) * 4)     = make_float2(d0, d1);
            *(float2*)(sm + P2_G + ((mt * 16 + 8 + r4) * SGST + col) * 4) = make_float2(d2, d3);
        }

        // ---- prefetch next step's acc-init (hidden under act + barriers) ----
        if (tloc + 1 < CHUNK) {
            size_t rbase = (size_t)(tloc + 1) * 4096 + b0 + mt * 16;
            #pragma unroll
            for (int i = 0; i < 8; i++) {
                int col = (wn * 8 + i) * 8 + c2;
                pa[i] = *(const float2*)(g_pre + (rbase + r4) * GATES + col);
                pb[i] = *(const float2*)(g_pre + (rbase + 8 + r4) * GATES + col);
            }
        }
        __syncthreads();

        // ---- activation + state update (512 thr x 8 cells) ----
        #pragma unroll 4
        for (int i = 0; i < 8; i++) {
            int cell = jb + 16 * i;
            float4 g4 = *(const float4*)(sm + P2_G + (arow * SGST + 4 * cell) * 4);
            float iv = sigf(g4.x), fv = sigf(g4.y);
            float gv = tanhfast(g4.z), ov = sigf(g4.w);
            float cc = fmaf(fv, creg[i], iv * gv);
            creg[i] = cc;
            float hh = ov * tanhfast(cc);
            __half hi, lo;
            split2(hh, hi, lo);
            *(__half*)(sm + P2_HH + arow * ROWB + cell * 2) = hi;
            *(__half*)(sm + P2_HL + arow * ROWB + cell * 2) = lo;
            if (tloc == CHUNK - 1) {
                // persist BOTH h and c across chunk boundary
                g_h[(b0 + arow) * 128 + cell] = hh;
                g_c[(b0 + arow) * 128 + cell] = cc;
                if (chunk == NCH - 1) {
                    float* out_h = out + (size_t)BATCH * TDIM * 5;
                    float* out_c = out_h + (size_t)BATCH * 128;
                    out_h[(b0 + arow) * 128 + cell] = hh;
                    out_c[(b0 + arow) * 128 + cell] = cc;
                }
            }
        }
        __syncthreads();

        // ---- y = h_new @ Wo^T + bo (160 threads; others run ahead to t+1) --
        if (tid < 160) {
            float s0 = 0.f, s1 = 0.f;
            const char* hh = sm + P2_HH + yr * ROWB;
            const char* hl = sm + P2_HL + yr * ROWB;
            const float* wrow = sWo + yd * 128;
            #pragma unroll 8
            for (int k = 0; k < 128; k += 2) {
                float2 fh = __half22float2(*(const __half2*)(hh + k * 2));
                float2 fl = __half22float2(*(const __half2*)(hl + k * 2));
                s0 = fmaf(fh.x + fl.x, wrow[k],     s0);
                s1 = fmaf(fh.y + fl.y, wrow[k + 1], s1);
            }
            int tg = chunk * CHUNK + tloc;
            out[((size_t)(b0 + yr) * TDIM + tg) * 5 + yd] = s0 + s1 + sbo[yd];
        }
    }
}

// ---------------------------------------------------------------------------
extern "C" void kernel_launch(void* const* d_in, const int* in_sizes, int n_in,
                              void* d_out, int out_size) {
    const float* xin = (const float*)d_in[0];
    const float* We  = (const float*)d_in[1];
    const float* be  = (const float*)d_in[2];
    const float* Wih = (const float*)d_in[3];
    const float* Whh = (const float*)d_in[4];
    const float* bih = (const float*)d_in[5];
    const float* bhh = (const float*)d_in[6];
    const float* Wo  = (const float*)d_in[7];
    const float* bo  = (const float*)d_in[8];
    float* out = (float*)d_out;

    cudaFuncSetAttribute(k_pre_tc, cudaFuncAttributeMaxDynamicSharedMemorySize, SMEM_P1);
    cudaFuncSetAttribute(k_recur,  cudaFuncAttributeMaxDynamicSharedMemorySize, SMEM_P2);

    k_prep<<<256, 256>>>(Wih, Whh, bih, bhh);
    k_zero<<<2048, 256>>>();
    for (int c = 0; c < NCH; c++) {
        k_pre_tc<<<dim3(128, 4), 256, SMEM_P1>>>(xin, We, be, c);
        k_recur<<<128, 512, SMEM_P2>>>(Wo, bo, out, c);
    }
}

// round 14
// speedup vs baseline: 2.7608x; 1.1072x over previous
#include <cuda_runtime.h>
#include <cuda_fp16.h>
#include <cstdint>

#define BATCH 4096
#define TDIM  1024
#define GATES 512
#define CHUNK 128
#define NCH   8

// ---------- device scratch --------------------------------------------------
__device__ float  g_pre[(size_t)BATCH * CHUNK * GATES];  // 1 GB staging (per chunk)
__device__ __half g_Bih[GATES * 128];                    // W_ih reordered [n][k] fp16
__device__ __half g_Bhh[GATES * 128];                    // W_hh reordered [n][k] fp16
__device__ float  g_bias[GATES];                         // b_ih+b_hh, reordered
__device__ float  g_h[BATCH * 128];
__device__ float  g_c[BATCH * 128];

// ---------- helpers ---------------------------------------------------------
__device__ __forceinline__ uint32_t smem_u32(const void* p) {
    uint32_t a;
    asm("{ .reg .u64 t; cvta.to.shared.u64 t, %1; cvt.u32.u64 %0, t; }" : "=r"(a) : "l"(p));
    return a;
}
__device__ __forceinline__ void ldm_x4(uint32_t* r, uint32_t addr) {
    asm volatile("ldmatrix.sync.aligned.m8n8.x4.shared.b16 {%0,%1,%2,%3},[%4];"
                 : "=r"(r[0]), "=r"(r[1]), "=r"(r[2]), "=r"(r[3]) : "r"(addr));
}
__device__ __forceinline__ void mma16816(float& d0, float& d1, float& d2, float& d3,
                                         uint32_t a0, uint32_t a1, uint32_t a2, uint32_t a3,
                                         uint32_t b0, uint32_t b1) {
    asm volatile("mma.sync.aligned.m16n8k16.row.col.f32.f16.f16.f32 "
                 "{%0,%1,%2,%3},{%4,%5,%6,%7},{%8,%9},{%0,%1,%2,%3};"
                 : "+f"(d0), "+f"(d1), "+f"(d2), "+f"(d3)
                 : "r"(a0), "r"(a1), "r"(a2), "r"(a3), "r"(b0), "r"(b1));
}
__device__ __forceinline__ float sigf(float x) {
    return __fdividef(1.f, 1.f + __expf(-x));
}
__device__ __forceinline__ float tanhfast(float x) {
    return 1.f - __fdividef(2.f, __expf(2.f * x) + 1.f);
}
// split x into hi (fp16) + lo (fp16 residual)
__device__ __forceinline__ void split2(float x, __half& hi, __half& lo) {
    hi = __float2half(x);
    lo = __float2half(x - __half2float(hi));
}

// row padding: 128 halves -> 272 bytes (row skew = 4 banks; conflict-free ldmatrix)
#define ROWB 272

// ---------- prep: reorder weights to [n][k], n = 4*cell + gate(i,f,g,o) -----
__global__ void k_prep(const float* __restrict__ Wih, const float* __restrict__ Whh,
                       const float* __restrict__ bih, const float* __restrict__ bhh) {
    int i = blockIdx.x * 256 + threadIdx.x;     // 512*128
    if (i >= GATES * 128) return;
    int n = i >> 7, k = i & 127;
    int go = (n & 3) * 128 + (n >> 2);          // original gate row
    g_Bih[n * 128 + k] = __float2half(Wih[go * 128 + k]);
    g_Bhh[n * 128 + k] = __float2half(Whh[go * 128 + k]);
    if (k == 0) g_bias[n] = bih[go] + bhh[go];
}

__global__ void k_zero() {
    int i = blockIdx.x * 256 + threadIdx.x;
    if (i < BATCH * 128) { g_h[i] = 0.f; g_c[i] = 0.f; }
}

// ---------- phase 1 (HMMA): pre = relu(x@We^T+be) @ Wih^T + bias ------------
#define P1_B    0                    // 512 rows x 272B = 139264
#define P1_EH   139264               // 128 x 272B = 34816
#define P1_EL   174080               // 128 x 272B = 34816
#define P1_BIAS 208896               // 512 f32
#define P1_WE   210944               // 256 f32
#define P1_BE   211968               // 128 f32
#define P1_X    212480               // 256 f32
#define SMEM_P1 213504

__global__ __launch_bounds__(256, 1)
void k_pre_tc(const float* __restrict__ xin, const float* __restrict__ We,
              const float* __restrict__ be, int chunk) {
    extern __shared__ char sm[];
    uint32_t smb = smem_u32(sm);
    float* sBias = (float*)(sm + P1_BIAS);
    float* sWe   = (float*)(sm + P1_WE);
    float* sbe   = (float*)(sm + P1_BE);
    float* sX    = (float*)(sm + P1_X);
    int tid = threadIdx.x;
    int w = tid >> 5, lane = tid & 31;
    int tloc = blockIdx.x;
    int tg = chunk * CHUNK + tloc;

    for (int idx = tid; idx < 8192; idx += 256) {
        int n = idx >> 4, kq = idx & 15;
        *(uint4*)(sm + P1_B + n * ROWB + kq * 16) = ((const uint4*)g_Bih)[idx];
    }
    for (int i = tid; i < 512; i += 256) sBias[i] = g_bias[i];
    if (tid < 256) sWe[tid] = We[tid];
    if (tid < 128) sbe[tid] = be[tid];

    int c2 = 2 * (lane & 3), r4 = lane >> 2;
    int lr = lane & 15, lh = lane >> 4;

    for (int it = 0; it < 8; it++) {
        int b0 = blockIdx.y * 1024 + it * 128;
        __syncthreads();
        if (tid < 128) {
            float2 v = ((const float2*)xin)[(size_t)(b0 + tid) * TDIM + tg];
            sX[2 * tid] = v.x; sX[2 * tid + 1] = v.y;
        }
        __syncthreads();
        for (int j = 0; j < 32; j++) {
            int p = j * 256 + tid;
            int r = p >> 6, k2 = p & 63;
            float x0 = sX[2 * r], x1 = sX[2 * r + 1];
            int k = 2 * k2;
            float e0 = fmaxf(fmaf(sWe[2 * k],     x0, fmaf(sWe[2 * k + 1], x1, sbe[k])),     0.f);
            float e1 = fmaxf(fmaf(sWe[2 * k + 2], x0, fmaf(sWe[2 * k + 3], x1, sbe[k + 1])), 0.f);
            __half h0, l0, h1, l1;
            split2(e0, h0, l0); split2(e1, h1, l1);
            *(__half2*)(sm + P1_EH + r * ROWB + k2 * 4) = __halves2half2(h0, h1);
            *(__half2*)(sm + P1_EL + r * ROWB + k2 * 4) = __halves2half2(l0, l1);
        }
        __syncthreads();

        uint32_t ah[8][4], al[8][4];
        uint32_t ahb = smb + P1_EH + (16 * w + lr) * ROWB + lh * 16;
        uint32_t alb = smb + P1_EL + (16 * w + lr) * ROWB + lh * 16;
        #pragma unroll
        for (int ks = 0; ks < 8; ks++) { ldm_x4(ah[ks], ahb + ks * 32); ldm_x4(al[ks], alb + ks * 32); }

        size_t grow = (size_t)tloc * 4096 + b0 + 16 * w + r4;
        #pragma unroll 2
        for (int nt = 0; nt < 64; nt++) {
            float2 bv = *(const float2*)(sBias + nt * 8 + c2);
            float d0 = bv.x, d1 = bv.y, d2 = bv.x, d3 = bv.y;
            uint32_t bbase = smb + P1_B + (nt * 8 + (lane & 7)) * ROWB + (lane >> 3) * 16;
            #pragma unroll
            for (int kp = 0; kp < 4; kp++) {
                uint32_t bf[4];
                ldm_x4(bf, bbase + kp * 64);
                mma16816(d0, d1, d2, d3, ah[2*kp][0], ah[2*kp][1], ah[2*kp][2], ah[2*kp][3], bf[0], bf[1]);
                mma16816(d0, d1, d2, d3, ah[2*kp+1][0], ah[2*kp+1][1], ah[2*kp+1][2], ah[2*kp+1][3], bf[2], bf[3]);
                mma16816(d0, d1, d2, d3, al[2*kp][0], al[2*kp][1], al[2*kp][2], al[2*kp][3], bf[0], bf[1]);
                mma16816(d0, d1, d2, d3, al[2*kp+1][0], al[2*kp+1][1], al[2*kp+1][2], al[2*kp+1][3], bf[2], bf[3]);
            }
            *(float2*)(g_pre + grow * GATES + nt * 8 + c2)       = make_float2(d0, d1);
            *(float2*)(g_pre + (grow + 8) * GATES + nt * 8 + c2) = make_float2(d2, d3);
        }
    }
}

// ---------- phase 2 (HMMA recurrence): 1 CTA = 32 batch rows, 512 threads ---
// In-register activation: lane pair (l, l^1) exchanges fragments via shfl.bfly
// so each lane owns a full (i,f,g,o) for one (row, cell). No gate smem buffer.
// H is double-buffered (tloc parity) -> ONE barrier per step.
#define P2_B   0                     // W_hh 512 x 272B = 139264
#define P2_H   139264                // 2 bufs x (HH 8704 + HL 8704) = 34816
#define HBUF   17408
#define P2_WO  174080                // 640 f32
#define P2_BO  176640                // 5 f32
#define SMEM_P2 176672

__global__ __launch_bounds__(512, 1)
void k_recur(const float* __restrict__ Wo, const float* __restrict__ bo,
             float* __restrict__ out, int chunk) {
    extern __shared__ char sm[];
    uint32_t smb = smem_u32(sm);
    float* sWo = (float*)(sm + P2_WO);
    float* sbo = (float*)(sm + P2_BO);
    int tid = threadIdx.x;
    int w = tid >> 5, lane = tid & 31;
    int mt = w >> 3, wn = w & 7;
    int b0 = blockIdx.x * 32;

    // W_hh [n][k] fp16 into padded rows
    for (int idx = tid; idx < 8192; idx += 512) {
        int n = idx >> 4, kq = idx & 15;
        *(uint4*)(sm + P2_B + n * ROWB + kq * 16) = ((const uint4*)g_Bhh)[idx];
    }
    // initial h -> buffer 1 (read buffer of step 0)
    for (int i = tid; i < 4096; i += 512) {
        int r = i >> 7, k = i & 127;
        __half hi, lo;
        split2(g_h[(b0 + r) * 128 + k], hi, lo);
        *(__half*)(sm + P2_H + HBUF + r * ROWB + k * 2) = hi;
        *(__half*)(sm + P2_H + HBUF + 8704 + r * ROWB + k * 2) = lo;
    }
    for (int i = tid; i < 640; i += 512) sWo[i] = Wo[i];
    if (tid < 5) sbo[tid] = bo[tid];

    int c2 = 2 * (lane & 3), r4 = lane >> 2;
    int lr = lane & 15, lh = lane >> 4;
    int par = lane & 1;                 // 0: row r4, 1: row r4+8
    int cb  = (lane >> 1) & 1;          // cell-within-ntile
    int row32 = mt * 16 + r4 + 8 * par; // owned row (0..31)
    int cell0 = wn * 16 + cb;           // owned cells: cell0 + 2*i

    float creg[8];
    #pragma unroll
    for (int i = 0; i < 8; i++)
        creg[i] = g_c[(b0 + row32) * 128 + cell0 + 2 * i];

    int yr = tid / 5, yd = tid - yr * 5;
    __syncthreads();

    // register double-buffer for g_pre acc-init (prefetch step 0)
    float2 pa[8], pb[8];
    {
        size_t rbase = (size_t)(b0 + mt * 16);
        #pragma unroll
        for (int i = 0; i < 8; i++) {
            int col = (wn * 8 + i) * 8 + c2;
            pa[i] = *(const float2*)(g_pre + (rbase + r4) * GATES + col);
            pb[i] = *(const float2*)(g_pre + (rbase + 8 + r4) * GATES + col);
        }
    }

    for (int tloc = 0; tloc < CHUNK; tloc++) {
        int wb = tloc & 1, rb = wb ^ 1;
        // ---- A-ldmatrix from read buffer ----
        uint32_t ah[8][4], al[8][4];
        uint32_t ahb = smb + P2_H + rb * HBUF + (mt * 16 + lr) * ROWB + lh * 16;
        uint32_t alb = ahb + 8704;
        #pragma unroll
        for (int ks = 0; ks < 8; ks++) { ldm_x4(ah[ks], ahb + ks * 32); ldm_x4(al[ks], alb + ks * 32); }

        char* hwh = sm + P2_H + wb * HBUF + row32 * ROWB;
        char* hwl = hwh + 8704;

        #pragma unroll
        for (int i = 0; i < 8; i++) {
            float d0 = pa[i].x, d1 = pa[i].y, d2 = pb[i].x, d3 = pb[i].y;
            uint32_t bbase = smb + P2_B + ((wn * 8 + i) * 8 + (lane & 7)) * ROWB
                             + (lane >> 3) * 16;
            #pragma unroll
            for (int kp = 0; kp < 4; kp++) {
                uint32_t bf[4];
                ldm_x4(bf, bbase + kp * 64);
                mma16816(d0, d1, d2, d3, ah[2*kp][0], ah[2*kp][1], ah[2*kp][2], ah[2*kp][3], bf[0], bf[1]);
                mma16816(d0, d1, d2, d3, ah[2*kp+1][0], ah[2*kp+1][1], ah[2*kp+1][2], ah[2*kp+1][3], bf[2], bf[3]);
                mma16816(d0, d1, d2, d3, al[2*kp][0], al[2*kp][1], al[2*kp][2], al[2*kp][3], bf[0], bf[1]);
                mma16816(d0, d1, d2, d3, al[2*kp+1][0], al[2*kp+1][1], al[2*kp+1][2], al[2*kp+1][3], bf[2], bf[3]);
            }
            // ---- fragment exchange: pair (l, l^1) completes (i,f,g,o) ----
            float e0 = __shfl_xor_sync(0xffffffffu, d0, 1);
            float e1 = __shfl_xor_sync(0xffffffffu, d1, 1);
            float e2 = __shfl_xor_sync(0xffffffffu, d2, 1);
            float e3 = __shfl_xor_sync(0xffffffffu, d3, 1);
            float gi = par ? e2 : d0;
            float gf = par ? e3 : d1;
            float gg = par ? d2 : e0;
            float go = par ? d3 : e1;
            // ---- activation + state update (in registers) ----
            float iv = sigf(gi), fv = sigf(gf);
            float gv = tanhfast(gg), ov = sigf(go);
            float cc = fmaf(fv, creg[i], iv * gv);
            creg[i] = cc;
            float hh = ov * tanhfast(cc);
            __half hhi, hlo;
            split2(hh, hhi, hlo);
            int cell = cell0 + 2 * i;
            *(__half*)(hwh + cell * 2) = hhi;
            *(__half*)(hwl + cell * 2) = hlo;
            if (tloc == CHUNK - 1) {
                g_h[(b0 + row32) * 128 + cell] = hh;
                g_c[(b0 + row32) * 128 + cell] = cc;
                if (chunk == NCH - 1) {
                    float* out_h = out + (size_t)BATCH * TDIM * 5;
                    float* out_c = out_h + (size_t)BATCH * 128;
                    out_h[(b0 + row32) * 128 + cell] = hh;
                    out_c[(b0 + row32) * 128 + cell] = cc;
                }
            }
        }

        // ---- prefetch next step's acc-init ----
        if (tloc + 1 < CHUNK) {
            size_t rbase = (size_t)(tloc + 1) * 4096 + b0 + mt * 16;
            #pragma unroll
            for (int i = 0; i < 8; i++) {
                int col = (wn * 8 + i) * 8 + c2;
                pa[i] = *(const float2*)(g_pre + (rbase + r4) * GATES + col);
                pb[i] = *(const float2*)(g_pre + (rbase + 8 + r4) * GATES + col);
            }
        }
        __syncthreads();   // H(t) writes visible; all H(t-1)/y reads done

        // ---- y = h_new @ Wo^T + bo (160 threads; reads write-buffer) ----
        if (tid < 160) {
            float s0 = 0.f, s1 = 0.f;
            const char* hh_ = sm + P2_H + wb * HBUF + yr * ROWB;
            const char* hl_ = hh_ + 8704;
            const float* wrow = sWo + yd * 128;
            #pragma unroll 8
            for (int k = 0; k < 128; k += 2) {
                float2 fh = __half22float2(*(const __half2*)(hh_ + k * 2));
                float2 fl = __half22float2(*(const __half2*)(hl_ + k * 2));
                s0 = fmaf(fh.x + fl.x, wrow[k],     s0);
                s1 = fmaf(fh.y + fl.y, wrow[k + 1], s1);
            }
            int tg = chunk * CHUNK + tloc;
            out[((size_t)(b0 + yr) * TDIM + tg) * 5 + yd] = s0 + s1 + sbo[yd];
        }
    }
}

// ---------------------------------------------------------------------------
extern "C" void kernel_launch(void* const* d_in, const int* in_sizes, int n_in,
                              void* d_out, int out_size) {
    const float* xin = (const float*)d_in[0];
    const float* We  = (const float*)d_in[1];
    const float* be  = (const float*)d_in[2];
    const float* Wih = (const float*)d_in[3];
    const float* Whh = (const float*)d_in[4];
    const float* bih = (const float*)d_in[5];
    const float* bhh = (const float*)d_in[6];
    const float* Wo  = (const float*)d_in[7];
    const float* bo  = (const float*)d_in[8];
    float* out = (float*)d_out;

    cudaFuncSetAttribute(k_pre_tc, cudaFuncAttributeMaxDynamicSharedMemorySize, SMEM_P1);
    cudaFuncSetAttribute(k_recur,  cudaFuncAttributeMaxDynamicSharedMemorySize, SMEM_P2);

    k_prep<<<256, 256>>>(Wih, Whh, bih, bhh);
    k_zero<<<2048, 256>>>();
    for (int c = 0; c < NCH; c++) {
        k_pre_tc<<<dim3(128, 4), 256, SMEM_P1>>>(xin, We, be, c);
        k_recur<<<128, 512, SMEM_P2>>>(Wo, bo, out, c);
    }
}